// round 8
// baseline (speedup 1.0000x reference)
#include <cuda_runtime.h>
#include <cuda_bf16.h>
#include <math.h>

// Problem constants
#define BB   64
#define TT   512
#define EE   256
#define HH   256
#define G4   1024
#define KK   10

// -------- device scratch ----------------------------------------------------
__device__ float g_pre[2u * 32768u * 1024u];          // [dir][t*64+b][4H]
__device__ float g_h[2u * 512u * 64u * 256u];         // [dir][t][b][h]
__device__ float g_logits[512u * 64u * 10u];          // [t][b][k]

// -------- f32x2 packed helpers ----------------------------------------------
__device__ __forceinline__ unsigned long long pk2(float x, float y) {
    unsigned long long r;
    asm("mov.b64 %0, {%1,%2};" : "=l"(r) : "f"(x), "f"(y));
    return r;
}
__device__ __forceinline__ void fma2(unsigned long long& d,
                                     unsigned long long a,
                                     unsigned long long b) {
    asm("fma.rn.f32x2 %0, %1, %2, %0;" : "+l"(d) : "l"(a), "l"(b));
}
__device__ __forceinline__ float2 up2(unsigned long long v) {
    float2 r;
    asm("mov.b64 {%0,%1}, %2;" : "=f"(r.x), "=f"(r.y) : "l"(v));
    return r;
}

__device__ __forceinline__ unsigned smem_u32(const void* p) {
    unsigned a;
    asm("{ .reg .u64 t; cvta.to.shared.u64 t, %1; cvt.u32.u64 %0, t; }"
        : "=r"(a) : "l"(p));
    return a;
}
__device__ __forceinline__ unsigned mapa_u32(unsigned laddr, unsigned peer) {
    unsigned r;
    asm("mapa.shared::cluster.u32 %0, %1, %2;" : "=r"(r) : "r"(laddr), "r"(peer));
    return r;
}
__device__ __forceinline__ void st_cluster_v4(unsigned addr, float4 v) {
    asm volatile("st.shared::cluster.v4.f32 [%0], {%1,%2,%3,%4};"
                 :: "r"(addr), "f"(v.x), "f"(v.y), "f"(v.z), "f"(v.w)
                 : "memory");
}

// -------- mbarrier helpers (cluster scope) -----------------------------------
__device__ __forceinline__ void mbar_init(unsigned addr, unsigned cnt) {
    asm volatile("mbarrier.init.shared.b64 [%0], %1;"
                 :: "r"(addr), "r"(cnt) : "memory");
}
__device__ __forceinline__ void mbar_arrive_remote(unsigned laddr, unsigned peer) {
    asm volatile("{ .reg .b32 ra;\n\t"
                 "mapa.shared::cluster.u32 ra, %0, %1;\n\t"
                 "mbarrier.arrive.release.cluster.shared::cluster.b64 _, [ra]; }"
                 :: "r"(laddr), "r"(peer) : "memory");
}
__device__ __forceinline__ void mbar_wait_acq(unsigned addr, unsigned parity) {
    asm volatile(
        "{ .reg .pred P;\n\t"
        "WAIT_%=:\n\t"
        "mbarrier.try_wait.parity.acquire.cluster.shared::cta.b64 P, [%0], %1, 0x989680;\n\t"
        "@P bra.uni DONE_%=;\n\t"
        "bra.uni WAIT_%=;\n\t"
        "DONE_%=: }"
        :: "r"(addr), "r"(parity) : "memory");
}
__device__ __forceinline__ void fence_cluster() {
    asm volatile("fence.acq_rel.cluster;" ::: "memory");
}

__global__ void dummy_kernel() {}

// ---------------------------------------------------------------------------
// Kernel A: fused embedding-gather + GEMM (unchanged from R6/R7)
// ---------------------------------------------------------------------------
__global__ void __launch_bounds__(256)
pregemm_kernel(const int* __restrict__ sent,
               const float* __restrict__ emb,
               const float* __restrict__ Wih_f,
               const float* __restrict__ b_f,
               const float* __restrict__ Wih_b,
               const float* __restrict__ b_b) {
    const int dir = blockIdx.z;
    const int n0  = blockIdx.x * 128;
    const int m0  = blockIdx.y * 128;
    const float* Wih  = dir ? Wih_b : Wih_f;
    const float* bias = dir ? b_b  : b_f;

    __shared__ float As[2][16][128];
    __shared__ float Bs[2][16][128];
    __shared__ int   toks[128];

    const int tid = threadIdx.x;
    if (tid < 128) {
        int m = m0 + tid;
        toks[tid] = sent[(m & 63) * TT + (m >> 6)];
    }
    __syncthreads();

    const int mA   = tid & 127;
    const int half = tid >> 7;
    const int ty   = tid >> 4;
    const int tx   = tid & 15;

    const float4* emb4 = (const float4*)emb;
    const float4* w4   = (const float4*)Wih;

    const size_t arow = (size_t)toks[mA] * 64;
    const size_t brow = (size_t)(n0 + mA) * 64;

    float acc[8][8];
#pragma unroll
    for (int i = 0; i < 8; ++i)
#pragma unroll
        for (int j = 0; j < 8; ++j) acc[i][j] = 0.f;

    float4 a0g = emb4[arow + half * 2 + 0];
    float4 a1g = emb4[arow + half * 2 + 1];
    float4 b0g = w4  [brow + half * 2 + 0];
    float4 b1g = w4  [brow + half * 2 + 1];

    int buf = 0;
    {
        const int kb = half * 8;
        As[0][kb+0][mA]=a0g.x; As[0][kb+1][mA]=a0g.y; As[0][kb+2][mA]=a0g.z; As[0][kb+3][mA]=a0g.w;
        As[0][kb+4][mA]=a1g.x; As[0][kb+5][mA]=a1g.y; As[0][kb+6][mA]=a1g.z; As[0][kb+7][mA]=a1g.w;
        Bs[0][kb+0][mA]=b0g.x; Bs[0][kb+1][mA]=b0g.y; Bs[0][kb+2][mA]=b0g.z; Bs[0][kb+3][mA]=b0g.w;
        Bs[0][kb+4][mA]=b1g.x; Bs[0][kb+5][mA]=b1g.y; Bs[0][kb+6][mA]=b1g.z; Bs[0][kb+7][mA]=b1g.w;
    }
    __syncthreads();

    for (int kc = 0; kc < 16; ++kc) {
        if (kc < 15) {
            const size_t kq = (size_t)(kc + 1) * 4 + half * 2;
            a0g = emb4[arow + kq];  a1g = emb4[arow + kq + 1];
            b0g = w4  [brow + kq];  b1g = w4  [brow + kq + 1];
        }
#pragma unroll
        for (int kk = 0; kk < 16; ++kk) {
            float4 aA = *(const float4*)&As[buf][kk][ty * 8];
            float4 aB = *(const float4*)&As[buf][kk][ty * 8 + 4];
            float4 bA = *(const float4*)&Bs[buf][kk][tx * 8];
            float4 bB = *(const float4*)&Bs[buf][kk][tx * 8 + 4];
            float av[8] = {aA.x, aA.y, aA.z, aA.w, aB.x, aB.y, aB.z, aB.w};
            float bv[8] = {bA.x, bA.y, bA.z, bA.w, bB.x, bB.y, bB.z, bB.w};
#pragma unroll
            for (int i = 0; i < 8; ++i)
#pragma unroll
                for (int j = 0; j < 8; ++j)
                    acc[i][j] += av[i] * bv[j];
        }
        if (kc < 15) {
            const int nb = buf ^ 1;
            const int kb = half * 8;
            As[nb][kb+0][mA]=a0g.x; As[nb][kb+1][mA]=a0g.y; As[nb][kb+2][mA]=a0g.z; As[nb][kb+3][mA]=a0g.w;
            As[nb][kb+4][mA]=a1g.x; As[nb][kb+5][mA]=a1g.y; As[nb][kb+6][mA]=a1g.z; As[nb][kb+7][mA]=a1g.w;
            Bs[nb][kb+0][mA]=b0g.x; Bs[nb][kb+1][mA]=b0g.y; Bs[nb][kb+2][mA]=b0g.z; Bs[nb][kb+3][mA]=b0g.w;
            Bs[nb][kb+4][mA]=b1g.x; Bs[nb][kb+5][mA]=b1g.y; Bs[nb][kb+6][mA]=b1g.z; Bs[nb][kb+7][mA]=b1g.w;
            __syncthreads();
            buf = nb;
        }
    }

    float4 bv0 = ((const float4*)bias)[(n0 >> 2) + tx * 2];
    float4 bv1 = ((const float4*)bias)[(n0 >> 2) + tx * 2 + 1];
    float4* out4 = (float4*)g_pre;
#pragma unroll
    for (int i = 0; i < 8; ++i) {
        const int m = m0 + ty * 8 + i;
        const size_t row = (size_t)dir * 32768 + m;
        float4 o0, o1;
        o0.x = acc[i][0] + bv0.x; o0.y = acc[i][1] + bv0.y;
        o0.z = acc[i][2] + bv0.z; o0.w = acc[i][3] + bv0.w;
        o1.x = acc[i][4] + bv1.x; o1.y = acc[i][5] + bv1.y;
        o1.z = acc[i][6] + bv1.z; o1.w = acc[i][7] + bv1.w;
        out4[row * 256 + (n0 >> 2) + tx * 2]     = o0;
        out4[row * 256 + (n0 >> 2) + tx * 2 + 1] = o1;
    }
}

// ---------------------------------------------------------------------------
// Kernel B: cluster recurrence with mbarrier full/consumed protocol
// (replaces per-step barrier.cluster: no L1 flush, HW-sleep waits).
// Buffers: read sH[p] at step it (p=it&1); push peers' sH[p^1].
//   full[q]: 8 arrivals -> data for buffer q present
//   cons[q]: 8 arrivals -> all CTAs finished reading buffer q (safe to overwrite)
// cons[1] pre-armed once at init (first write to buf 1 has no prior readers).
// ---------------------------------------------------------------------------
#define SW_PITCH 260
#define SH_PITCH 268
#define OFF_SH   (4 * 32 * SW_PITCH)
#define OFF_STG  (OFF_SH + 2 * 8 * SH_PITCH)
#define OFF_BAR_B ((OFF_STG + 256) * 4)
#define REC_SMEM_BYTES (OFF_BAR_B + 64)

__device__ __forceinline__ float sigm(float x) { return 1.f / (1.f + expf(-x)); }

__global__ void __cluster_dims__(8, 1, 1)
lstm_rec_kernel(const float* __restrict__ Whh_f,
                const float* __restrict__ Whh_b) {
    const int cid    = blockIdx.x >> 3;
    const int r      = blockIdx.x & 7;
    const int dir    = cid >> 3;
    const int bgroup = cid & 7;
    const int tid    = threadIdx.x;       // 256
    const int u      = tid >> 3;
    const int bl     = tid & 7;
    const int bglob  = bgroup * 8 + bl;
    const int hu     = r * 32 + u;

    const float* Whh = dir ? Whh_b : Whh_f;

    extern __shared__ float sm[];
    float* sW   = sm;
    float* sH   = sm + OFF_SH;
    float* sStg = sm + OFF_STG;

    const unsigned sbase    = smem_u32(sm);
    const unsigned bar_full = sbase + OFF_BAR_B;        // full[0], full[1]
    const unsigned bar_cons = sbase + OFF_BAR_B + 16;   // cons[0], cons[1]

    const float4* whh4 = (const float4*)Whh;
    for (int e = tid; e < 8192; e += 256) {
        int g = e >> 11, rem = e & 2047, uu = rem >> 6, k4 = rem & 63;
        float4 v = whh4[(size_t)(g * 256 + r * 32 + uu) * 64 + k4];
        *(float4*)&sW[(g * 32 + uu) * SW_PITCH + k4 * 4] = v;
    }
    for (int e = tid; e < 8 * SH_PITCH; e += 256) sH[e] = 0.f;
    if (tid == 0) {
        mbar_init(bar_full + 0, 8);
        mbar_init(bar_full + 8, 8);
        mbar_init(bar_cons + 0, 8);
        mbar_init(bar_cons + 8, 8);
    }
    __syncthreads();

    // cluster sync: all inits + zeroed buffers visible before any remote op
    asm volatile("barrier.cluster.arrive.aligned;" ::: "memory");
    asm volatile("barrier.cluster.wait.aligned;" ::: "memory");

    // pre-arm cons[1]: buffer 1 has no prior readers
    if (tid == 0)
        for (unsigned peer = 0; peer < 8; ++peer)
            mbar_arrive_remote(bar_cons + 8, peer);

    const unsigned sh_base = smem_u32(sH);

    const ulonglong2* w0 = (const ulonglong2*)&sW[(0 * 32 + u) * SW_PITCH];
    const ulonglong2* w1 = (const ulonglong2*)&sW[(1 * 32 + u) * SW_PITCH];
    const ulonglong2* w2 = (const ulonglong2*)&sW[(2 * 32 + u) * SW_PITCH];
    const ulonglong2* w3 = (const ulonglong2*)&sW[(3 * 32 + u) * SW_PITCH];

    const int t0 = dir ? 511 : 0;
    size_t pb = ((size_t)dir * 32768 + (size_t)t0 * 64 + bglob) * 1024 + hu;
    float4 pr;
    pr.x = __ldcg(&g_pre[pb]);
    pr.y = __ldcg(&g_pre[pb + 256]);
    pr.z = __ldcg(&g_pre[pb + 512]);
    pr.w = __ldcg(&g_pre[pb + 768]);

    float c = 0.f;
    int full_par[2] = {0, 0};
    int cons_par[2] = {0, 0};

    for (int it = 0; it < 512; ++it) {
        const int t = dir ? (511 - it) : it;
        const int p = it & 1;

        if (it > 0) {                 // wait for peers' h data for this step
            mbar_wait_acq(bar_full + p * 8, (unsigned)full_par[p]);
            full_par[p] ^= 1;
        }

        unsigned long long a0 = pk2(pr.x, 0.f);
        unsigned long long a1 = pk2(pr.y, 0.f);
        unsigned long long a2 = pk2(pr.z, 0.f);
        unsigned long long a3 = pk2(pr.w, 0.f);

        if (it < 511) {
            const int tn = dir ? (t - 1) : (t + 1);
            size_t pbn = ((size_t)dir * 32768 + (size_t)tn * 64 + bglob) * 1024 + hu;
            pr.x = __ldcg(&g_pre[pbn]);
            pr.y = __ldcg(&g_pre[pbn + 256]);
            pr.z = __ldcg(&g_pre[pbn + 512]);
            pr.w = __ldcg(&g_pre[pbn + 768]);
        }

        const ulonglong2* hrow = (const ulonglong2*)&sH[(p * 8 + bl) * SH_PITCH];

#pragma unroll 8
        for (int k4 = 0; k4 < 64; ++k4) {
            ulonglong2 h2 = hrow[k4];
            ulonglong2 v0 = w0[k4];
            ulonglong2 v1 = w1[k4];
            ulonglong2 v2 = w2[k4];
            ulonglong2 v3 = w3[k4];
            fma2(a0, v0.x, h2.x); fma2(a1, v1.x, h2.x);
            fma2(a2, v2.x, h2.x); fma2(a3, v3.x, h2.x);
            fma2(a0, v0.y, h2.y); fma2(a1, v1.y, h2.y);
            fma2(a2, v2.y, h2.y); fma2(a3, v3.y, h2.y);
        }

        float2 q;
        q = up2(a0); float gi = q.x + q.y;
        q = up2(a1); float gf = q.x + q.y;
        q = up2(a2); float gg = q.x + q.y;
        q = up2(a3); float go = q.x + q.y;

        float iv = sigm(gi), fv = sigm(gf), gv = tanhf(gg), ov = sigm(go);
        c = fv * c + iv * gv;
        float hval = ov * tanhf(c);

        g_h[(((size_t)(dir * 512 + t)) * 64 + bglob) * 256 + hu] = hval;

        sStg[bl * 32 + u] = hval;
        __syncthreads();    // all reads of sH[p] done; sStg ready

        if (it < 511) {
            // signal: this CTA finished reading buffer p
            if (tid == 0) {
                fence_cluster();
                for (unsigned peer = 0; peer < 8; ++peer)
                    mbar_arrive_remote(bar_cons + p * 8, peer);
            }
            // wait: all CTAs finished reading buffer p^1 (safe to overwrite)
            mbar_wait_acq(bar_cons + (p ^ 1) * 8, (unsigned)cons_par[p ^ 1]);
            cons_par[p ^ 1] ^= 1;

            // push h slice to all 8 cluster CTAs' sH[p^1]
            const float4* stg4 = (const float4*)sStg;
#pragma unroll
            for (int e = tid; e < 512; e += 256) {
                int peer = e >> 6, f4i = e & 63;
                int bb = f4i >> 3, uq = f4i & 7;
                float4 v = stg4[f4i];
                unsigned laddr = sh_base
                               + (unsigned)(((p ^ 1) * 8 + bb) * SH_PITCH * 4)
                               + (unsigned)(r * 128 + uq * 16);
                st_cluster_v4(mapa_u32(laddr, (unsigned)peer), v);
            }
            fence_cluster();
            __syncthreads();
            if (tid == 0)
                for (unsigned peer = 0; peer < 8; ++peer)
                    mbar_arrive_remote(bar_full + (p ^ 1) * 8, peer);
        }
    }

    // no CTA may exit while peers might still write into its smem
    asm volatile("barrier.cluster.arrive.aligned;" ::: "memory");
    asm volatile("barrier.cluster.wait.aligned;" ::: "memory");
}

// ---------------------------------------------------------------------------
// Kernel C: logits (unchanged)
// ---------------------------------------------------------------------------
__global__ void logits_kernel(const float* __restrict__ Wout,
                              const float* __restrict__ bout) {
    const int t = blockIdx.x;
    __shared__ float sWo[10 * 512];
    __shared__ float sCH[64 * 65];
    __shared__ float sBo[10];

    const int tid = threadIdx.x;      // 640
    for (int idx = tid; idx < 5120; idx += 640) sWo[idx] = Wout[idx];
    if (tid < 10) sBo[tid] = bout[tid];

    const int n = tid / 64, bb = tid & 63;
    float acc = 0.f;
    const float4* gh4 = (const float4*)g_h;

    for (int ch = 0; ch < 8; ++ch) {
        __syncthreads();
        for (int idx = tid; idx < 1024; idx += 640) {
            int b_ = idx >> 4, q = idx & 15;
            int d = ch >> 2;
            int hid4 = (ch & 3) * 16 + q;
            float4 v = gh4[(((size_t)d * 512 + t) * 64 + b_) * 64 + hid4];
            float* dst = &sCH[(q * 4) * 65 + b_];
            dst[0]   = v.x;  dst[65]  = v.y;
            dst[130] = v.z;  dst[195] = v.w;
        }
        __syncthreads();
#pragma unroll 8
        for (int r = 0; r < 64; ++r)
            acc += sWo[n * 512 + ch * 64 + r] * sCH[r * 65 + bb];
    }
    g_logits[((size_t)t * 64 + bb) * 10 + n] = acc + sBo[n];
}

// ---------------------------------------------------------------------------
// Kernel D: Viterbi (unchanged)
// ---------------------------------------------------------------------------
__global__ void viterbi_kernel(const float* __restrict__ trans,
                               float* __restrict__ out) {
    const int tid  = threadIdx.x;
    const int w    = tid >> 5;
    const int lane = tid & 31;
    const int b    = blockIdx.x * 4 + w;

    __shared__ float         sLT[2][16][4][10];
    __shared__ float         sCur[4][32];
    __shared__ unsigned char bp[4][512][10];
    __shared__ float         tr[100];

    for (int i = tid; i < 100; i += 128) tr[i] = trans[i];

    const int bbase = blockIdx.x * 4;
    float stage[5];
#pragma unroll
    for (int s = 0; s < 5; ++s) {
        int idx = tid + s * 128;
        int t_off = idx / 40, rem = idx % 40;
        int b_off = rem / 10, k = rem % 10;
        stage[s] = g_logits[((size_t)(0 + t_off) * 64 + bbase + b_off) * 10 + k];
    }
#pragma unroll
    for (int s = 0; s < 5; ++s) {
        int idx = tid + s * 128;
        int t_off = idx / 40, rem = idx % 40;
        int b_off = rem / 10, k = rem % 10;
        sLT[0][t_off][b_off][k] = stage[s];
    }
    __syncthreads();

    float trc[10];
#pragma unroll
    for (int i = 0; i < 10; ++i) trc[i] = (lane < 10) ? tr[i * 10 + lane] : 0.f;

    float cur = (lane < 10) ? sLT[0][0][w][lane] : -1e30f;

    for (int cchunk = 0; cchunk < 32; ++cchunk) {
        const int buf = cchunk & 1;
        if (cchunk < 31) {
            const int tb = (cchunk + 1) * 16;
#pragma unroll
            for (int s = 0; s < 5; ++s) {
                int idx = tid + s * 128;
                int t_off = idx / 40, rem = idx % 40;
                int b_off = rem / 10, k = rem % 10;
                stage[s] = g_logits[((size_t)(tb + t_off) * 64 + bbase + b_off) * 10 + k];
            }
        }

        const int tstart = (cchunk == 0) ? 1 : 0;
#pragma unroll 4
        for (int ti = tstart; ti < 16; ++ti) {
            const int t = cchunk * 16 + ti;
            if (lane < 10) sCur[w][lane] = cur;
            __syncwarp();
            float best = sCur[w][0] + trc[0];
            int bi = 0;
#pragma unroll
            for (int i = 1; i < 10; ++i) {
                float v = sCur[w][i] + trc[i];
                if (v > best) { best = v; bi = i; }
            }
            __syncwarp();
            if (lane < 10) {
                cur = sLT[buf][ti][w][lane] + best;
                bp[w][t][lane] = (unsigned char)bi;
            }
        }

        if (cchunk < 31) {
            __syncthreads();
#pragma unroll
            for (int s = 0; s < 5; ++s) {
                int idx = tid + s * 128;
                int t_off = idx / 40, rem = idx % 40;
                int b_off = rem / 10, k = rem % 10;
                sLT[buf ^ 1][t_off][b_off][k] = stage[s];
            }
            __syncthreads();
        }
    }

    if (lane < 10) sCur[w][lane] = cur;
    __syncwarp();
    if (lane == 0) {
        float best = sCur[w][0]; int last = 0;
#pragma unroll
        for (int i = 1; i < 10; ++i)
            if (sCur[w][i] > best) { best = sCur[w][i]; last = i; }
        out[b] = best;
        float* po = out + 64 + (size_t)b * 512;
        int tag = last;
        po[511] = (float)tag;
        for (int t = 511; t >= 1; --t) {
            tag = bp[w][t][tag];
            po[t - 1] = (float)tag;
        }
    }
}

// ---------------------------------------------------------------------------
extern "C" void kernel_launch(void* const* d_in, const int* in_sizes, int n_in,
                              void* d_out, int out_size) {
    const int*   sent  = (const int*)  d_in[0];
    const float* emb   = (const float*)d_in[2];
    const float* Wih_f = (const float*)d_in[3];
    const float* Whh_f = (const float*)d_in[4];
    const float* b_f   = (const float*)d_in[5];
    const float* Wih_b = (const float*)d_in[6];
    const float* Whh_b = (const float*)d_in[7];
    const float* b_b   = (const float*)d_in[8];
    const float* W_out = (const float*)d_in[9];
    const float* b_out = (const float*)d_in[10];
    const float* trans = (const float*)d_in[11];
    float* out = (float*)d_out;

    cudaFuncSetAttribute(lstm_rec_kernel,
                         cudaFuncAttributeMaxDynamicSharedMemorySize,
                         REC_SMEM_BYTES);

    // lstm_rec_kernel in 4th launch slot -> ncu captures IT this round
    pregemm_kernel<<<dim3(8, 256, 2), 256>>>(sent, emb, Wih_f, b_f, Wih_b, b_b);
    dummy_kernel<<<1, 32>>>();
    dummy_kernel<<<1, 32>>>();
    lstm_rec_kernel<<<128, 256, REC_SMEM_BYTES>>>(Whh_f, Whh_b);
    logits_kernel<<<512, 640>>>(W_out, b_out);
    viterbi_kernel<<<16, 128>>>(trans, out);
}

// round 9
// speedup vs baseline: 1.0266x; 1.0266x over previous
#include <cuda_runtime.h>
#include <cuda_bf16.h>
#include <math.h>

// Problem constants
#define BB   64
#define TT   512
#define EE   256
#define HH   256
#define G4   1024
#define KK   10

// -------- device scratch ----------------------------------------------------
__device__ float g_pre[2u * 32768u * 1024u];          // [dir][t*64+b][4H]
__device__ float g_h[2u * 512u * 64u * 256u];         // [dir][t][b][h]
__device__ float g_logits[512u * 64u * 10u];          // [t][b][k]

// -------- f32x2 packed helpers ----------------------------------------------
__device__ __forceinline__ unsigned long long pk2(float x, float y) {
    unsigned long long r;
    asm("mov.b64 %0, {%1,%2};" : "=l"(r) : "f"(x), "f"(y));
    return r;
}
__device__ __forceinline__ void fma2(unsigned long long& d,
                                     unsigned long long a,
                                     unsigned long long b) {
    asm("fma.rn.f32x2 %0, %1, %2, %0;" : "+l"(d) : "l"(a), "l"(b));
}
__device__ __forceinline__ float2 up2(unsigned long long v) {
    float2 r;
    asm("mov.b64 {%0,%1}, %2;" : "=f"(r.x), "=f"(r.y) : "l"(v));
    return r;
}

__device__ __forceinline__ unsigned smem_u32(const void* p) {
    unsigned a;
    asm("{ .reg .u64 t; cvta.to.shared.u64 t, %1; cvt.u32.u64 %0, t; }"
        : "=r"(a) : "l"(p));
    return a;
}
__device__ __forceinline__ unsigned mapa_u32(unsigned laddr, unsigned peer) {
    unsigned r;
    asm("mapa.shared::cluster.u32 %0, %1, %2;" : "=r"(r) : "r"(laddr), "r"(peer));
    return r;
}
__device__ __forceinline__ void st_cluster_v4(unsigned addr, float4 v) {
    asm volatile("st.shared::cluster.v4.f32 [%0], {%1,%2,%3,%4};"
                 :: "r"(addr), "f"(v.x), "f"(v.y), "f"(v.z), "f"(v.w)
                 : "memory");
}

__global__ void dummy_kernel() {}

// ---------------------------------------------------------------------------
// Kernel A: fused embedding-gather + GEMM (byte-identical to R6/R7: 902us)
// ---------------------------------------------------------------------------
__global__ void __launch_bounds__(256)
pregemm_kernel(const int* __restrict__ sent,
               const float* __restrict__ emb,
               const float* __restrict__ Wih_f,
               const float* __restrict__ b_f,
               const float* __restrict__ Wih_b,
               const float* __restrict__ b_b) {
    const int dir = blockIdx.z;
    const int n0  = blockIdx.x * 128;
    const int m0  = blockIdx.y * 128;
    const float* Wih  = dir ? Wih_b : Wih_f;
    const float* bias = dir ? b_b  : b_f;

    __shared__ float As[2][16][128];
    __shared__ float Bs[2][16][128];
    __shared__ int   toks[128];

    const int tid = threadIdx.x;
    if (tid < 128) {
        int m = m0 + tid;
        toks[tid] = sent[(m & 63) * TT + (m >> 6)];
    }
    __syncthreads();

    const int mA   = tid & 127;
    const int half = tid >> 7;
    const int ty   = tid >> 4;
    const int tx   = tid & 15;

    const float4* emb4 = (const float4*)emb;
    const float4* w4   = (const float4*)Wih;

    const size_t arow = (size_t)toks[mA] * 64;
    const size_t brow = (size_t)(n0 + mA) * 64;

    float acc[8][8];
#pragma unroll
    for (int i = 0; i < 8; ++i)
#pragma unroll
        for (int j = 0; j < 8; ++j) acc[i][j] = 0.f;

    float4 a0g = emb4[arow + half * 2 + 0];
    float4 a1g = emb4[arow + half * 2 + 1];
    float4 b0g = w4  [brow + half * 2 + 0];
    float4 b1g = w4  [brow + half * 2 + 1];

    int buf = 0;
    {
        const int kb = half * 8;
        As[0][kb+0][mA]=a0g.x; As[0][kb+1][mA]=a0g.y; As[0][kb+2][mA]=a0g.z; As[0][kb+3][mA]=a0g.w;
        As[0][kb+4][mA]=a1g.x; As[0][kb+5][mA]=a1g.y; As[0][kb+6][mA]=a1g.z; As[0][kb+7][mA]=a1g.w;
        Bs[0][kb+0][mA]=b0g.x; Bs[0][kb+1][mA]=b0g.y; Bs[0][kb+2][mA]=b0g.z; Bs[0][kb+3][mA]=b0g.w;
        Bs[0][kb+4][mA]=b1g.x; Bs[0][kb+5][mA]=b1g.y; Bs[0][kb+6][mA]=b1g.z; Bs[0][kb+7][mA]=b1g.w;
    }
    __syncthreads();

    for (int kc = 0; kc < 16; ++kc) {
        if (kc < 15) {
            const size_t kq = (size_t)(kc + 1) * 4 + half * 2;
            a0g = emb4[arow + kq];  a1g = emb4[arow + kq + 1];
            b0g = w4  [brow + kq];  b1g = w4  [brow + kq + 1];
        }
#pragma unroll
        for (int kk = 0; kk < 16; ++kk) {
            float4 aA = *(const float4*)&As[buf][kk][ty * 8];
            float4 aB = *(const float4*)&As[buf][kk][ty * 8 + 4];
            float4 bA = *(const float4*)&Bs[buf][kk][tx * 8];
            float4 bB = *(const float4*)&Bs[buf][kk][tx * 8 + 4];
            float av[8] = {aA.x, aA.y, aA.z, aA.w, aB.x, aB.y, aB.z, aB.w};
            float bv[8] = {bA.x, bA.y, bA.z, bA.w, bB.x, bB.y, bB.z, bB.w};
#pragma unroll
            for (int i = 0; i < 8; ++i)
#pragma unroll
                for (int j = 0; j < 8; ++j)
                    acc[i][j] += av[i] * bv[j];
        }
        if (kc < 15) {
            const int nb = buf ^ 1;
            const int kb = half * 8;
            As[nb][kb+0][mA]=a0g.x; As[nb][kb+1][mA]=a0g.y; As[nb][kb+2][mA]=a0g.z; As[nb][kb+3][mA]=a0g.w;
            As[nb][kb+4][mA]=a1g.x; As[nb][kb+5][mA]=a1g.y; As[nb][kb+6][mA]=a1g.z; As[nb][kb+7][mA]=a1g.w;
            Bs[nb][kb+0][mA]=b0g.x; Bs[nb][kb+1][mA]=b0g.y; Bs[nb][kb+2][mA]=b0g.z; Bs[nb][kb+3][mA]=b0g.w;
            Bs[nb][kb+4][mA]=b1g.x; Bs[nb][kb+5][mA]=b1g.y; Bs[nb][kb+6][mA]=b1g.z; Bs[nb][kb+7][mA]=b1g.w;
            __syncthreads();
            buf = nb;
        }
    }

    float4 bv0 = ((const float4*)bias)[(n0 >> 2) + tx * 2];
    float4 bv1 = ((const float4*)bias)[(n0 >> 2) + tx * 2 + 1];
    float4* out4 = (float4*)g_pre;
#pragma unroll
    for (int i = 0; i < 8; ++i) {
        const int m = m0 + ty * 8 + i;
        const size_t row = (size_t)dir * 32768 + m;
        float4 o0, o1;
        o0.x = acc[i][0] + bv0.x; o0.y = acc[i][1] + bv0.y;
        o0.z = acc[i][2] + bv0.z; o0.w = acc[i][3] + bv0.w;
        o1.x = acc[i][4] + bv1.x; o1.y = acc[i][5] + bv1.y;
        o1.z = acc[i][6] + bv1.z; o1.w = acc[i][7] + bv1.w;
        out4[row * 256 + (n0 >> 2) + tx * 2]     = o0;
        out4[row * 256 + (n0 >> 2) + tx * 2 + 1] = o1;
    }
}

// ---------------------------------------------------------------------------
// Kernel B: cluster recurrence, R6 sync skeleton (barrier.cluster), NEW:
//   512 threads, split-K (kh = tid&1 takes half the K range),
//   shuffle-combine partials, fast activations, RAW-safe FMA order.
// thread map: u = tid>>4 (32 units), bl = (tid>>1)&7 (8 batches), kh = tid&1.
// ---------------------------------------------------------------------------
#define SW_PITCH 260
#define SH_PITCH 268
#define OFF_SH   (4 * 32 * SW_PITCH)
#define OFF_STG  (OFF_SH + 2 * 8 * SH_PITCH)
#define REC_SMEM_BYTES ((OFF_STG + 256) * 4)

__device__ __forceinline__ float fsigm(float x) {
    return __fdividef(1.f, 1.f + __expf(-x));
}
__device__ __forceinline__ float ftanh(float x) {
    float e = __expf(-2.f * fabsf(x));
    float r = __fdividef(1.f - e, 1.f + e);
    return copysignf(r, x);
}

__global__ void __cluster_dims__(8, 1, 1) __launch_bounds__(512)
lstm_rec_kernel(const float* __restrict__ Whh_f,
                const float* __restrict__ Whh_b) {
    const int cid    = blockIdx.x >> 3;
    const int r      = blockIdx.x & 7;
    const int dir    = cid >> 3;
    const int bgroup = cid & 7;
    const int tid    = threadIdx.x;       // 512
    const int u      = tid >> 4;          // 0..31
    const int bl     = (tid >> 1) & 7;    // 0..7
    const int kh     = tid & 1;           // K half
    const int bglob  = bgroup * 8 + bl;
    const int hu     = r * 32 + u;

    const float* Whh = dir ? Whh_b : Whh_f;

    extern __shared__ float sm[];
    float* sW   = sm;
    float* sH   = sm + OFF_SH;
    float* sStg = sm + OFF_STG;

    const float4* whh4 = (const float4*)Whh;
    for (int e = tid; e < 8192; e += 512) {
        int g = e >> 11, rem = e & 2047, uu = rem >> 6, k4 = rem & 63;
        float4 v = whh4[(size_t)(g * 256 + r * 32 + uu) * 64 + k4];
        *(float4*)&sW[(g * 32 + uu) * SW_PITCH + k4 * 4] = v;
    }
    for (int e = tid; e < 8 * SH_PITCH; e += 512) sH[e] = 0.f;
    __syncthreads();

    asm volatile("barrier.cluster.arrive.aligned;" ::: "memory");
    asm volatile("barrier.cluster.wait.aligned;" ::: "memory");

    const unsigned sh_base = smem_u32(sH);

    // weight pointers: this thread's unit, K half kh (128 floats = 32 u2)
    const ulonglong2* w0 = (const ulonglong2*)&sW[(0 * 32 + u) * SW_PITCH + kh * 128];
    const ulonglong2* w1 = (const ulonglong2*)&sW[(1 * 32 + u) * SW_PITCH + kh * 128];
    const ulonglong2* w2 = (const ulonglong2*)&sW[(2 * 32 + u) * SW_PITCH + kh * 128];
    const ulonglong2* w3 = (const ulonglong2*)&sW[(3 * 32 + u) * SW_PITCH + kh * 128];

    const int t0 = dir ? 511 : 0;
    size_t pb = ((size_t)dir * 32768 + (size_t)t0 * 64 + bglob) * 1024 + hu;
    float4 pr;
    pr.x = __ldcg(&g_pre[pb]);
    pr.y = __ldcg(&g_pre[pb + 256]);
    pr.z = __ldcg(&g_pre[pb + 512]);
    pr.w = __ldcg(&g_pre[pb + 768]);

    float c = 0.f;

    for (int it = 0; it < 512; ++it) {
        const int t = dir ? (511 - it) : it;
        const int p = it & 1;

        unsigned long long a0 = 0ull, a1 = 0ull, a2 = 0ull, a3 = 0ull;

        float4 prn;
        if (it < 511) {
            const int tn = dir ? (t - 1) : (t + 1);
            size_t pbn = ((size_t)dir * 32768 + (size_t)tn * 64 + bglob) * 1024 + hu;
            prn.x = __ldcg(&g_pre[pbn]);
            prn.y = __ldcg(&g_pre[pbn + 256]);
            prn.z = __ldcg(&g_pre[pbn + 512]);
            prn.w = __ldcg(&g_pre[pbn + 768]);
        }

        const ulonglong2* hrow =
            (const ulonglong2*)&sH[(p * 8 + bl) * SH_PITCH + kh * 128];

#pragma unroll 8
        for (int k4 = 0; k4 < 32; ++k4) {
            ulonglong2 h2 = hrow[k4];
            ulonglong2 v0 = w0[k4];
            ulonglong2 v1 = w1[k4];
            ulonglong2 v2 = w2[k4];
            ulonglong2 v3 = w3[k4];
            fma2(a0, v0.x, h2.x); fma2(a1, v1.x, h2.x);
            fma2(a2, v2.x, h2.x); fma2(a3, v3.x, h2.x);
            fma2(a0, v0.y, h2.y); fma2(a1, v1.y, h2.y);
            fma2(a2, v2.y, h2.y); fma2(a3, v3.y, h2.y);
        }

        float2 q;
        q = up2(a0); float s0 = q.x + q.y;
        q = up2(a1); float s1 = q.x + q.y;
        q = up2(a2); float s2 = q.x + q.y;
        q = up2(a3); float s3 = q.x + q.y;
        // combine K halves (partner = adjacent lane)
        s0 += __shfl_xor_sync(0xFFFFFFFFu, s0, 1);
        s1 += __shfl_xor_sync(0xFFFFFFFFu, s1, 1);
        s2 += __shfl_xor_sync(0xFFFFFFFFu, s2, 1);
        s3 += __shfl_xor_sync(0xFFFFFFFFu, s3, 1);

        float gi = s0 + pr.x;
        float gf = s1 + pr.y;
        float gg = s2 + pr.z;
        float go = s3 + pr.w;

        float iv = fsigm(gi), fv = fsigm(gf), gv = ftanh(gg), ov = fsigm(go);
        c = fv * c + iv * gv;
        float hval = ov * ftanh(c);

        if (kh == 0) {
            g_h[(((size_t)(dir * 512 + t)) * 64 + bglob) * 256 + hu] = hval;
            sStg[bl * 32 + u] = hval;
        }
        __syncthreads();

        if (it < 511) {
            // push h slice to all 8 cluster CTAs' sH[p^1] (1 st per thread)
            {
                int peer = tid >> 6, f4i = tid & 63;
                int bb = f4i >> 3, uq = f4i & 7;
                float4 v = ((const float4*)sStg)[f4i];
                unsigned laddr = sh_base
                               + (unsigned)(((p ^ 1) * 8 + bb) * SH_PITCH * 4)
                               + (unsigned)(r * 128 + uq * 16);
                st_cluster_v4(mapa_u32(laddr, (unsigned)peer), v);
            }
            asm volatile("barrier.cluster.arrive.aligned;" ::: "memory");
            asm volatile("barrier.cluster.wait.aligned;" ::: "memory");
        }
        pr = prn;
    }

    asm volatile("barrier.cluster.arrive.aligned;" ::: "memory");
    asm volatile("barrier.cluster.wait.aligned;" ::: "memory");
}

// ---------------------------------------------------------------------------
// Kernel C: logits (unchanged)
// ---------------------------------------------------------------------------
__global__ void logits_kernel(const float* __restrict__ Wout,
                              const float* __restrict__ bout) {
    const int t = blockIdx.x;
    __shared__ float sWo[10 * 512];
    __shared__ float sCH[64 * 65];
    __shared__ float sBo[10];

    const int tid = threadIdx.x;      // 640
    for (int idx = tid; idx < 5120; idx += 640) sWo[idx] = Wout[idx];
    if (tid < 10) sBo[tid] = bout[tid];

    const int n = tid / 64, bb = tid & 63;
    float acc = 0.f;
    const float4* gh4 = (const float4*)g_h;

    for (int ch = 0; ch < 8; ++ch) {
        __syncthreads();
        for (int idx = tid; idx < 1024; idx += 640) {
            int b_ = idx >> 4, q = idx & 15;
            int d = ch >> 2;
            int hid4 = (ch & 3) * 16 + q;
            float4 v = gh4[(((size_t)d * 512 + t) * 64 + b_) * 64 + hid4];
            float* dst = &sCH[(q * 4) * 65 + b_];
            dst[0]   = v.x;  dst[65]  = v.y;
            dst[130] = v.z;  dst[195] = v.w;
        }
        __syncthreads();
#pragma unroll 8
        for (int r = 0; r < 64; ++r)
            acc += sWo[n * 512 + ch * 64 + r] * sCH[r * 65 + bb];
    }
    g_logits[((size_t)t * 64 + bb) * 10 + n] = acc + sBo[n];
}

// ---------------------------------------------------------------------------
// Kernel D: Viterbi (unchanged)
// ---------------------------------------------------------------------------
__global__ void viterbi_kernel(const float* __restrict__ trans,
                               float* __restrict__ out) {
    const int tid  = threadIdx.x;
    const int w    = tid >> 5;
    const int lane = tid & 31;
    const int b    = blockIdx.x * 4 + w;

    __shared__ float         sLT[2][16][4][10];
    __shared__ float         sCur[4][32];
    __shared__ unsigned char bp[4][512][10];
    __shared__ float         tr[100];

    for (int i = tid; i < 100; i += 128) tr[i] = trans[i];

    const int bbase = blockIdx.x * 4;
    float stage[5];
#pragma unroll
    for (int s = 0; s < 5; ++s) {
        int idx = tid + s * 128;
        int t_off = idx / 40, rem = idx % 40;
        int b_off = rem / 10, k = rem % 10;
        stage[s] = g_logits[((size_t)(0 + t_off) * 64 + bbase + b_off) * 10 + k];
    }
#pragma unroll
    for (int s = 0; s < 5; ++s) {
        int idx = tid + s * 128;
        int t_off = idx / 40, rem = idx % 40;
        int b_off = rem / 10, k = rem % 10;
        sLT[0][t_off][b_off][k] = stage[s];
    }
    __syncthreads();

    float trc[10];
#pragma unroll
    for (int i = 0; i < 10; ++i) trc[i] = (lane < 10) ? tr[i * 10 + lane] : 0.f;

    float cur = (lane < 10) ? sLT[0][0][w][lane] : -1e30f;

    for (int cchunk = 0; cchunk < 32; ++cchunk) {
        const int buf = cchunk & 1;
        if (cchunk < 31) {
            const int tb = (cchunk + 1) * 16;
#pragma unroll
            for (int s = 0; s < 5; ++s) {
                int idx = tid + s * 128;
                int t_off = idx / 40, rem = idx % 40;
                int b_off = rem / 10, k = rem % 10;
                stage[s] = g_logits[((size_t)(tb + t_off) * 64 + bbase + b_off) * 10 + k];
            }
        }

        const int tstart = (cchunk == 0) ? 1 : 0;
#pragma unroll 4
        for (int ti = tstart; ti < 16; ++ti) {
            const int t = cchunk * 16 + ti;
            if (lane < 10) sCur[w][lane] = cur;
            __syncwarp();
            float best = sCur[w][0] + trc[0];
            int bi = 0;
#pragma unroll
            for (int i = 1; i < 10; ++i) {
                float v = sCur[w][i] + trc[i];
                if (v > best) { best = v; bi = i; }
            }
            __syncwarp();
            if (lane < 10) {
                cur = sLT[buf][ti][w][lane] + best;
                bp[w][t][lane] = (unsigned char)bi;
            }
        }

        if (cchunk < 31) {
            __syncthreads();
#pragma unroll
            for (int s = 0; s < 5; ++s) {
                int idx = tid + s * 128;
                int t_off = idx / 40, rem = idx % 40;
                int b_off = rem / 10, k = rem % 10;
                sLT[buf ^ 1][t_off][b_off][k] = stage[s];
            }
            __syncthreads();
        }
    }

    if (lane < 10) sCur[w][lane] = cur;
    __syncwarp();
    if (lane == 0) {
        float best = sCur[w][0]; int last = 0;
#pragma unroll
        for (int i = 1; i < 10; ++i)
            if (sCur[w][i] > best) { best = sCur[w][i]; last = i; }
        out[b] = best;
        float* po = out + 64 + (size_t)b * 512;
        int tag = last;
        po[511] = (float)tag;
        for (int t = 511; t >= 1; --t) {
            tag = bp[w][t][tag];
            po[t - 1] = (float)tag;
        }
    }
}

// ---------------------------------------------------------------------------
extern "C" void kernel_launch(void* const* d_in, const int* in_sizes, int n_in,
                              void* d_out, int out_size) {
    const int*   sent  = (const int*)  d_in[0];
    const float* emb   = (const float*)d_in[2];
    const float* Wih_f = (const float*)d_in[3];
    const float* Whh_f = (const float*)d_in[4];
    const float* b_f   = (const float*)d_in[5];
    const float* Wih_b = (const float*)d_in[6];
    const float* Whh_b = (const float*)d_in[7];
    const float* b_b   = (const float*)d_in[8];
    const float* W_out = (const float*)d_in[9];
    const float* b_out = (const float*)d_in[10];
    const float* trans = (const float*)d_in[11];
    float* out = (float*)d_out;

    cudaFuncSetAttribute(lstm_rec_kernel,
                         cudaFuncAttributeMaxDynamicSharedMemorySize,
                         REC_SMEM_BYTES);

    pregemm_kernel<<<dim3(8, 256, 2), 256>>>(sent, emb, Wih_f, b_f, Wih_b, b_b);
    dummy_kernel<<<1, 32>>>();
    dummy_kernel<<<1, 32>>>();
    lstm_rec_kernel<<<128, 512, REC_SMEM_BYTES>>>(Whh_f, Whh_b);
    logits_kernel<<<512, 640>>>(W_out, b_out);
    viterbi_kernel<<<16, 128>>>(trans, out);
}

// round 10
// speedup vs baseline: 1.6931x; 1.6493x over previous
#include <cuda_runtime.h>
#include <cuda_bf16.h>
#include <math.h>

// Problem constants
#define BB   64
#define TT   512
#define EE   256
#define HH   256
#define G4   1024
#define KK   10

// -------- device scratch ----------------------------------------------------
__device__ float g_pre[2u * 32768u * 1024u];          // [dir][t*64+b][4H]
__device__ float g_h[2u * 512u * 64u * 256u];         // [dir][t][b][h]
__device__ float g_logits[512u * 64u * 10u];          // [t][b][k]

__device__ __forceinline__ unsigned smem_u32(const void* p) {
    unsigned a;
    asm("{ .reg .u64 t; cvta.to.shared.u64 t, %1; cvt.u32.u64 %0, t; }"
        : "=r"(a) : "l"(p));
    return a;
}
__device__ __forceinline__ unsigned mapa_u32(unsigned laddr, unsigned peer) {
    unsigned r;
    asm("mapa.shared::cluster.u32 %0, %1, %2;" : "=r"(r) : "r"(laddr), "r"(peer));
    return r;
}
__device__ __forceinline__ void st_cluster_v4(unsigned addr, float4 v) {
    asm volatile("st.shared::cluster.v4.f32 [%0], {%1,%2,%3,%4};"
                 :: "r"(addr), "f"(v.x), "f"(v.y), "f"(v.z), "f"(v.w)
                 : "memory");
}

__global__ void dummy_kernel() {}

// ---------------------------------------------------------------------------
// Kernel A: fused embedding-gather + GEMM (byte-identical to the 902us config)
// ---------------------------------------------------------------------------
__global__ void __launch_bounds__(256)
pregemm_kernel(const int* __restrict__ sent,
               const float* __restrict__ emb,
               const float* __restrict__ Wih_f,
               const float* __restrict__ b_f,
               const float* __restrict__ Wih_b,
               const float* __restrict__ b_b) {
    const int dir = blockIdx.z;
    const int n0  = blockIdx.x * 128;
    const int m0  = blockIdx.y * 128;
    const float* Wih  = dir ? Wih_b : Wih_f;
    const float* bias = dir ? b_b  : b_f;

    __shared__ float As[2][16][128];
    __shared__ float Bs[2][16][128];
    __shared__ int   toks[128];

    const int tid = threadIdx.x;
    if (tid < 128) {
        int m = m0 + tid;
        toks[tid] = sent[(m & 63) * TT + (m >> 6)];
    }
    __syncthreads();

    const int mA   = tid & 127;
    const int half = tid >> 7;
    const int ty   = tid >> 4;
    const int tx   = tid & 15;

    const float4* emb4 = (const float4*)emb;
    const float4* w4   = (const float4*)Wih;

    const size_t arow = (size_t)toks[mA] * 64;
    const size_t brow = (size_t)(n0 + mA) * 64;

    float acc[8][8];
#pragma unroll
    for (int i = 0; i < 8; ++i)
#pragma unroll
        for (int j = 0; j < 8; ++j) acc[i][j] = 0.f;

    float4 a0g = emb4[arow + half * 2 + 0];
    float4 a1g = emb4[arow + half * 2 + 1];
    float4 b0g = w4  [brow + half * 2 + 0];
    float4 b1g = w4  [brow + half * 2 + 1];

    int buf = 0;
    {
        const int kb = half * 8;
        As[0][kb+0][mA]=a0g.x; As[0][kb+1][mA]=a0g.y; As[0][kb+2][mA]=a0g.z; As[0][kb+3][mA]=a0g.w;
        As[0][kb+4][mA]=a1g.x; As[0][kb+5][mA]=a1g.y; As[0][kb+6][mA]=a1g.z; As[0][kb+7][mA]=a1g.w;
        Bs[0][kb+0][mA]=b0g.x; Bs[0][kb+1][mA]=b0g.y; Bs[0][kb+2][mA]=b0g.z; Bs[0][kb+3][mA]=b0g.w;
        Bs[0][kb+4][mA]=b1g.x; Bs[0][kb+5][mA]=b1g.y; Bs[0][kb+6][mA]=b1g.z; Bs[0][kb+7][mA]=b1g.w;
    }
    __syncthreads();

    for (int kc = 0; kc < 16; ++kc) {
        if (kc < 15) {
            const size_t kq = (size_t)(kc + 1) * 4 + half * 2;
            a0g = emb4[arow + kq];  a1g = emb4[arow + kq + 1];
            b0g = w4  [brow + kq];  b1g = w4  [brow + kq + 1];
        }
#pragma unroll
        for (int kk = 0; kk < 16; ++kk) {
            float4 aA = *(const float4*)&As[buf][kk][ty * 8];
            float4 aB = *(const float4*)&As[buf][kk][ty * 8 + 4];
            float4 bA = *(const float4*)&Bs[buf][kk][tx * 8];
            float4 bB = *(const float4*)&Bs[buf][kk][tx * 8 + 4];
            float av[8] = {aA.x, aA.y, aA.z, aA.w, aB.x, aB.y, aB.z, aB.w};
            float bv[8] = {bA.x, bA.y, bA.z, bA.w, bB.x, bB.y, bB.z, bB.w};
#pragma unroll
            for (int i = 0; i < 8; ++i)
#pragma unroll
                for (int j = 0; j < 8; ++j)
                    acc[i][j] += av[i] * bv[j];
        }
        if (kc < 15) {
            const int nb = buf ^ 1;
            const int kb = half * 8;
            As[nb][kb+0][mA]=a0g.x; As[nb][kb+1][mA]=a0g.y; As[nb][kb+2][mA]=a0g.z; As[nb][kb+3][mA]=a0g.w;
            As[nb][kb+4][mA]=a1g.x; As[nb][kb+5][mA]=a1g.y; As[nb][kb+6][mA]=a1g.z; As[nb][kb+7][mA]=a1g.w;
            Bs[nb][kb+0][mA]=b0g.x; Bs[nb][kb+1][mA]=b0g.y; Bs[nb][kb+2][mA]=b0g.z; Bs[nb][kb+3][mA]=b0g.w;
            Bs[nb][kb+4][mA]=b1g.x; Bs[nb][kb+5][mA]=b1g.y; Bs[nb][kb+6][mA]=b1g.z; Bs[nb][kb+7][mA]=b1g.w;
            __syncthreads();
            buf = nb;
        }
    }

    float4 bv0 = ((const float4*)bias)[(n0 >> 2) + tx * 2];
    float4 bv1 = ((const float4*)bias)[(n0 >> 2) + tx * 2 + 1];
    float4* out4 = (float4*)g_pre;
#pragma unroll
    for (int i = 0; i < 8; ++i) {
        const int m = m0 + ty * 8 + i;
        const size_t row = (size_t)dir * 32768 + m;
        float4 o0, o1;
        o0.x = acc[i][0] + bv0.x; o0.y = acc[i][1] + bv0.y;
        o0.z = acc[i][2] + bv0.z; o0.w = acc[i][3] + bv0.w;
        o1.x = acc[i][4] + bv1.x; o1.y = acc[i][5] + bv1.y;
        o1.z = acc[i][6] + bv1.z; o1.w = acc[i][7] + bv1.w;
        out4[row * 256 + (n0 >> 2) + tx * 2]     = o0;
        out4[row * 256 + (n0 >> 2) + tx * 2 + 1] = o1;
    }
}

// ---------------------------------------------------------------------------
// Kernel B: cluster recurrence, REGISTER-RESIDENT WEIGHTS.
// 128 blocks = 16 clusters(8) = (2 dir x 8 bgroups); CTA r owns units
// [r*32, r*32+32), 8 batches. 256 threads: u = tid>>3 (32 units),
// kq = tid&7 (k-slice: k in {kq*4 + j*32 + e}).
// Weights (4 gates x 32 k = 128 floats) live in registers across all 512
// steps; per step only 64 conflict-free h-LDS.128 + 1024 reg FFMA, then
// 3-round shfl_xor reduce over kq. Sync/push skeleton = R5 (5294us, known
// good): sStg -> st.shared::cluster push -> barrier.cluster arrive+wait.
// ---------------------------------------------------------------------------
#define SH_PITCH 268

__device__ __forceinline__ float fsigm(float x) {
    return __fdividef(1.f, 1.f + __expf(-x));
}
__device__ __forceinline__ float ftanh(float x) {
    float e = __expf(-2.f * fabsf(x));
    float r = __fdividef(1.f - e, 1.f + e);
    return copysignf(r, x);
}

__global__ void __cluster_dims__(8, 1, 1) __launch_bounds__(256)
lstm_rec_kernel(const float* __restrict__ Whh_f,
                const float* __restrict__ Whh_b) {
    const int cid    = blockIdx.x >> 3;
    const int r      = blockIdx.x & 7;
    const int dir    = cid >> 3;
    const int bgroup = cid & 7;
    const int tid    = threadIdx.x;       // 256
    const int u      = tid >> 3;          // 0..31
    const int kq     = tid & 7;           // k-slice / epilogue batch
    const int bglob  = bgroup * 8 + kq;
    const int hu     = r * 32 + u;

    const float* Whh = dir ? Whh_b : Whh_f;

    __shared__ __align__(16) float sH[2 * 8 * SH_PITCH];   // 17152 B
    __shared__ __align__(16) float sStg[256];               // [b][u]

    // ---- load this thread's weights into registers (once) ----
    const float4* whh4 = (const float4*)Whh;
    float4 w[4][8];
#pragma unroll
    for (int g = 0; g < 4; ++g)
#pragma unroll
        for (int j = 0; j < 8; ++j)
            w[g][j] = whh4[((size_t)(g * 256 + hu)) * 64 + kq + j * 8];

    for (int e = tid; e < 2 * 8 * SH_PITCH; e += 256) sH[e] = 0.f;
    __syncthreads();

    asm volatile("barrier.cluster.arrive.aligned;" ::: "memory");
    asm volatile("barrier.cluster.wait.aligned;" ::: "memory");

    const unsigned sh_base = smem_u32(sH);

    // g_pre prefetch for first step (epilogue role: (hu, bglob))
    const int t0 = dir ? 511 : 0;
    size_t pb = ((size_t)dir * 32768 + (size_t)t0 * 64 + bglob) * 1024 + hu;
    float4 pr;
    pr.x = __ldcg(&g_pre[pb]);
    pr.y = __ldcg(&g_pre[pb + 256]);
    pr.z = __ldcg(&g_pre[pb + 512]);
    pr.w = __ldcg(&g_pre[pb + 768]);

    float c = 0.f;

    for (int it = 0; it < 512; ++it) {
        const int t = dir ? (511 - it) : it;
        const int p = it & 1;

        // prefetch next step's g_pre (hidden under the k-loop)
        float4 prn;
        if (it < 511) {
            const int tn = dir ? (t - 1) : (t + 1);
            size_t pbn = ((size_t)dir * 32768 + (size_t)tn * 64 + bglob) * 1024 + hu;
            prn.x = __ldcg(&g_pre[pbn]);
            prn.y = __ldcg(&g_pre[pbn + 256]);
            prn.z = __ldcg(&g_pre[pbn + 512]);
            prn.w = __ldcg(&g_pre[pbn + 768]);
        }

        // ---- main product: acc[g][b] += w[g][:] . h[b][:] (k-slice) ----
        float acc[4][8];
#pragma unroll
        for (int g = 0; g < 4; ++g)
#pragma unroll
            for (int b = 0; b < 8; ++b) acc[g][b] = 0.f;

        const float* hb = &sH[p * 8 * SH_PITCH + kq * 4];
#pragma unroll
        for (int j = 0; j < 8; ++j) {
#pragma unroll
            for (int b = 0; b < 8; ++b) {
                float4 h4 = *(const float4*)&hb[b * SH_PITCH + j * 32];
#pragma unroll
                for (int g = 0; g < 4; ++g) {
                    acc[g][b] = fmaf(w[g][j].x, h4.x,
                                fmaf(w[g][j].y, h4.y,
                                fmaf(w[g][j].z, h4.z,
                                fmaf(w[g][j].w, h4.w, acc[g][b]))));
                }
            }
        }

        // ---- reduce over the 8 kq slices (butterfly within warp) ----
#pragma unroll
        for (int g = 0; g < 4; ++g)
#pragma unroll
            for (int b = 0; b < 8; ++b) {
                float v = acc[g][b];
                v += __shfl_xor_sync(0xFFFFFFFFu, v, 1);
                v += __shfl_xor_sync(0xFFFFFFFFu, v, 2);
                v += __shfl_xor_sync(0xFFFFFFFFu, v, 4);
                acc[g][b] = v;
            }

        // select this thread's batch (b == kq)
        float s[4];
#pragma unroll
        for (int g = 0; g < 4; ++g) {
            float v = acc[g][0];
#pragma unroll
            for (int b = 1; b < 8; ++b) v = (kq == b) ? acc[g][b] : v;
            s[g] = v;
        }

        float gi = s[0] + pr.x;
        float gf = s[1] + pr.y;
        float gg = s[2] + pr.z;
        float go = s[3] + pr.w;

        float iv = fsigm(gi), fv = fsigm(gf), gv = ftanh(gg), ov = fsigm(go);
        c = fv * c + iv * gv;
        float hval = ov * ftanh(c);

        g_h[(((size_t)(dir * 512 + t)) * 64 + bglob) * 256 + hu] = hval;

        sStg[kq * 32 + u] = hval;
        __syncthreads();

        if (it < 511) {
            const float4* stg4 = (const float4*)sStg;
#pragma unroll
            for (int e = tid; e < 512; e += 256) {
                int peer = e >> 6, f4i = e & 63;
                int bb = f4i >> 3, uq = f4i & 7;
                float4 v = stg4[f4i];
                unsigned laddr = sh_base
                               + (unsigned)(((p ^ 1) * 8 + bb) * SH_PITCH * 4)
                               + (unsigned)(r * 128 + uq * 16);
                st_cluster_v4(mapa_u32(laddr, (unsigned)peer), v);
            }
            asm volatile("barrier.cluster.arrive.aligned;" ::: "memory");
            asm volatile("barrier.cluster.wait.aligned;" ::: "memory");
        }
        pr = prn;
    }

    asm volatile("barrier.cluster.arrive.aligned;" ::: "memory");
    asm volatile("barrier.cluster.wait.aligned;" ::: "memory");
}

// ---------------------------------------------------------------------------
// Kernel C: logits (unchanged)
// ---------------------------------------------------------------------------
__global__ void logits_kernel(const float* __restrict__ Wout,
                              const float* __restrict__ bout) {
    const int t = blockIdx.x;
    __shared__ float sWo[10 * 512];
    __shared__ float sCH[64 * 65];
    __shared__ float sBo[10];

    const int tid = threadIdx.x;      // 640
    for (int idx = tid; idx < 5120; idx += 640) sWo[idx] = Wout[idx];
    if (tid < 10) sBo[tid] = bout[tid];

    const int n = tid / 64, bb = tid & 63;
    float acc = 0.f;
    const float4* gh4 = (const float4*)g_h;

    for (int ch = 0; ch < 8; ++ch) {
        __syncthreads();
        for (int idx = tid; idx < 1024; idx += 640) {
            int b_ = idx >> 4, q = idx & 15;
            int d = ch >> 2;
            int hid4 = (ch & 3) * 16 + q;
            float4 v = gh4[(((size_t)d * 512 + t) * 64 + b_) * 64 + hid4];
            float* dst = &sCH[(q * 4) * 65 + b_];
            dst[0]   = v.x;  dst[65]  = v.y;
            dst[130] = v.z;  dst[195] = v.w;
        }
        __syncthreads();
#pragma unroll 8
        for (int r = 0; r < 64; ++r)
            acc += sWo[n * 512 + ch * 64 + r] * sCH[r * 65 + bb];
    }
    g_logits[((size_t)t * 64 + bb) * 10 + n] = acc + sBo[n];
}

// ---------------------------------------------------------------------------
// Kernel D: Viterbi (unchanged, 63us)
// ---------------------------------------------------------------------------
__global__ void viterbi_kernel(const float* __restrict__ trans,
                               float* __restrict__ out) {
    const int tid  = threadIdx.x;
    const int w    = tid >> 5;
    const int lane = tid & 31;
    const int b    = blockIdx.x * 4 + w;

    __shared__ float         sLT[2][16][4][10];
    __shared__ float         sCur[4][32];
    __shared__ unsigned char bp[4][512][10];
    __shared__ float         tr[100];

    for (int i = tid; i < 100; i += 128) tr[i] = trans[i];

    const int bbase = blockIdx.x * 4;
    float stage[5];
#pragma unroll
    for (int s = 0; s < 5; ++s) {
        int idx = tid + s * 128;
        int t_off = idx / 40, rem = idx % 40;
        int b_off = rem / 10, k = rem % 10;
        stage[s] = g_logits[((size_t)(0 + t_off) * 64 + bbase + b_off) * 10 + k];
    }
#pragma unroll
    for (int s = 0; s < 5; ++s) {
        int idx = tid + s * 128;
        int t_off = idx / 40, rem = idx % 40;
        int b_off = rem / 10, k = rem % 10;
        sLT[0][t_off][b_off][k] = stage[s];
    }
    __syncthreads();

    float trc[10];
#pragma unroll
    for (int i = 0; i < 10; ++i) trc[i] = (lane < 10) ? tr[i * 10 + lane] : 0.f;

    float cur = (lane < 10) ? sLT[0][0][w][lane] : -1e30f;

    for (int cchunk = 0; cchunk < 32; ++cchunk) {
        const int buf = cchunk & 1;
        if (cchunk < 31) {
            const int tb = (cchunk + 1) * 16;
#pragma unroll
            for (int s = 0; s < 5; ++s) {
                int idx = tid + s * 128;
                int t_off = idx / 40, rem = idx % 40;
                int b_off = rem / 10, k = rem % 10;
                stage[s] = g_logits[((size_t)(tb + t_off) * 64 + bbase + b_off) * 10 + k];
            }
        }

        const int tstart = (cchunk == 0) ? 1 : 0;
#pragma unroll 4
        for (int ti = tstart; ti < 16; ++ti) {
            const int t = cchunk * 16 + ti;
            if (lane < 10) sCur[w][lane] = cur;
            __syncwarp();
            float best = sCur[w][0] + trc[0];
            int bi = 0;
#pragma unroll
            for (int i = 1; i < 10; ++i) {
                float v = sCur[w][i] + trc[i];
                if (v > best) { best = v; bi = i; }
            }
            __syncwarp();
            if (lane < 10) {
                cur = sLT[buf][ti][w][lane] + best;
                bp[w][t][lane] = (unsigned char)bi;
            }
        }

        if (cchunk < 31) {
            __syncthreads();
#pragma unroll
            for (int s = 0; s < 5; ++s) {
                int idx = tid + s * 128;
                int t_off = idx / 40, rem = idx % 40;
                int b_off = rem / 10, k = rem % 10;
                sLT[buf ^ 1][t_off][b_off][k] = stage[s];
            }
            __syncthreads();
        }
    }

    if (lane < 10) sCur[w][lane] = cur;
    __syncwarp();
    if (lane == 0) {
        float best = sCur[w][0]; int last = 0;
#pragma unroll
        for (int i = 1; i < 10; ++i)
            if (sCur[w][i] > best) { best = sCur[w][i]; last = i; }
        out[b] = best;
        float* po = out + 64 + (size_t)b * 512;
        int tag = last;
        po[511] = (float)tag;
        for (int t = 511; t >= 1; --t) {
            tag = bp[w][t][tag];
            po[t - 1] = (float)tag;
        }
    }
}

// ---------------------------------------------------------------------------
extern "C" void kernel_launch(void* const* d_in, const int* in_sizes, int n_in,
                              void* d_out, int out_size) {
    const int*   sent  = (const int*)  d_in[0];
    const float* emb   = (const float*)d_in[2];
    const float* Wih_f = (const float*)d_in[3];
    const float* Whh_f = (const float*)d_in[4];
    const float* b_f   = (const float*)d_in[5];
    const float* Wih_b = (const float*)d_in[6];
    const float* Whh_b = (const float*)d_in[7];
    const float* b_b   = (const float*)d_in[8];
    const float* W_out = (const float*)d_in[9];
    const float* b_out = (const float*)d_in[10];
    const float* trans = (const float*)d_in[11];
    float* out = (float*)d_out;

    // dummies keep pregemm in ncu's captured slot (clock sanity check)
    dummy_kernel<<<1, 32>>>();
    dummy_kernel<<<1, 32>>>();
    dummy_kernel<<<1, 32>>>();
    pregemm_kernel<<<dim3(8, 256, 2), 256>>>(sent, emb, Wih_f, b_f, Wih_b, b_b);
    lstm_rec_kernel<<<128, 256>>>(Whh_f, Whh_b);
    logits_kernel<<<512, 640>>>(W_out, b_out);
    viterbi_kernel<<<16, 128>>>(trans, out);
}

// round 11
// speedup vs baseline: 2.3118x; 1.3654x over previous
#include <cuda_runtime.h>
#include <cuda_bf16.h>
#include <math.h>

// Problem constants
#define BB   64
#define TT   512
#define EE   256
#define HH   256
#define G4   1024
#define KK   10

// -------- device scratch ----------------------------------------------------
__device__ float g_pre[2u * 32768u * 1024u];          // [dir][t*64+b][4H]
__device__ float g_h[2u * 512u * 64u * 256u];         // [dir][t][b][h]
__device__ float g_logits[512u * 64u * 10u];          // [t][b][k]
__device__ unsigned g_bar;

__global__ void init_kernel() { g_bar = 0u; }
__global__ void dummy_kernel() {}

// ---------------------------------------------------------------------------
// Kernel A: fused embedding-gather + GEMM (byte-identical to the 902us config)
// ---------------------------------------------------------------------------
__global__ void __launch_bounds__(256)
pregemm_kernel(const int* __restrict__ sent,
               const float* __restrict__ emb,
               const float* __restrict__ Wih_f,
               const float* __restrict__ b_f,
               const float* __restrict__ Wih_b,
               const float* __restrict__ b_b) {
    const int dir = blockIdx.z;
    const int n0  = blockIdx.x * 128;
    const int m0  = blockIdx.y * 128;
    const float* Wih  = dir ? Wih_b : Wih_f;
    const float* bias = dir ? b_b  : b_f;

    __shared__ float As[2][16][128];
    __shared__ float Bs[2][16][128];
    __shared__ int   toks[128];

    const int tid = threadIdx.x;
    if (tid < 128) {
        int m = m0 + tid;
        toks[tid] = sent[(m & 63) * TT + (m >> 6)];
    }
    __syncthreads();

    const int mA   = tid & 127;
    const int half = tid >> 7;
    const int ty   = tid >> 4;
    const int tx   = tid & 15;

    const float4* emb4 = (const float4*)emb;
    const float4* w4   = (const float4*)Wih;

    const size_t arow = (size_t)toks[mA] * 64;
    const size_t brow = (size_t)(n0 + mA) * 64;

    float acc[8][8];
#pragma unroll
    for (int i = 0; i < 8; ++i)
#pragma unroll
        for (int j = 0; j < 8; ++j) acc[i][j] = 0.f;

    float4 a0g = emb4[arow + half * 2 + 0];
    float4 a1g = emb4[arow + half * 2 + 1];
    float4 b0g = w4  [brow + half * 2 + 0];
    float4 b1g = w4  [brow + half * 2 + 1];

    int buf = 0;
    {
        const int kb = half * 8;
        As[0][kb+0][mA]=a0g.x; As[0][kb+1][mA]=a0g.y; As[0][kb+2][mA]=a0g.z; As[0][kb+3][mA]=a0g.w;
        As[0][kb+4][mA]=a1g.x; As[0][kb+5][mA]=a1g.y; As[0][kb+6][mA]=a1g.z; As[0][kb+7][mA]=a1g.w;
        Bs[0][kb+0][mA]=b0g.x; Bs[0][kb+1][mA]=b0g.y; Bs[0][kb+2][mA]=b0g.z; Bs[0][kb+3][mA]=b0g.w;
        Bs[0][kb+4][mA]=b1g.x; Bs[0][kb+5][mA]=b1g.y; Bs[0][kb+6][mA]=b1g.z; Bs[0][kb+7][mA]=b1g.w;
    }
    __syncthreads();

    for (int kc = 0; kc < 16; ++kc) {
        if (kc < 15) {
            const size_t kq = (size_t)(kc + 1) * 4 + half * 2;
            a0g = emb4[arow + kq];  a1g = emb4[arow + kq + 1];
            b0g = w4  [brow + kq];  b1g = w4  [brow + kq + 1];
        }
#pragma unroll
        for (int kk = 0; kk < 16; ++kk) {
            float4 aA = *(const float4*)&As[buf][kk][ty * 8];
            float4 aB = *(const float4*)&As[buf][kk][ty * 8 + 4];
            float4 bA = *(const float4*)&Bs[buf][kk][tx * 8];
            float4 bB = *(const float4*)&Bs[buf][kk][tx * 8 + 4];
            float av[8] = {aA.x, aA.y, aA.z, aA.w, aB.x, aB.y, aB.z, aB.w};
            float bv[8] = {bA.x, bA.y, bA.z, bA.w, bB.x, bB.y, bB.z, bB.w};
#pragma unroll
            for (int i = 0; i < 8; ++i)
#pragma unroll
                for (int j = 0; j < 8; ++j)
                    acc[i][j] += av[i] * bv[j];
        }
        if (kc < 15) {
            const int nb = buf ^ 1;
            const int kb = half * 8;
            As[nb][kb+0][mA]=a0g.x; As[nb][kb+1][mA]=a0g.y; As[nb][kb+2][mA]=a0g.z; As[nb][kb+3][mA]=a0g.w;
            As[nb][kb+4][mA]=a1g.x; As[nb][kb+5][mA]=a1g.y; As[nb][kb+6][mA]=a1g.z; As[nb][kb+7][mA]=a1g.w;
            Bs[nb][kb+0][mA]=b0g.x; Bs[nb][kb+1][mA]=b0g.y; Bs[nb][kb+2][mA]=b0g.z; Bs[nb][kb+3][mA]=b0g.w;
            Bs[nb][kb+4][mA]=b1g.x; Bs[nb][kb+5][mA]=b1g.y; Bs[nb][kb+6][mA]=b1g.z; Bs[nb][kb+7][mA]=b1g.w;
            __syncthreads();
            buf = nb;
        }
    }

    float4 bv0 = ((const float4*)bias)[(n0 >> 2) + tx * 2];
    float4 bv1 = ((const float4*)bias)[(n0 >> 2) + tx * 2 + 1];
    float4* out4 = (float4*)g_pre;
#pragma unroll
    for (int i = 0; i < 8; ++i) {
        const int m = m0 + ty * 8 + i;
        const size_t row = (size_t)dir * 32768 + m;
        float4 o0, o1;
        o0.x = acc[i][0] + bv0.x; o0.y = acc[i][1] + bv0.y;
        o0.z = acc[i][2] + bv0.z; o0.w = acc[i][3] + bv0.w;
        o1.x = acc[i][4] + bv1.x; o1.y = acc[i][5] + bv1.y;
        o1.z = acc[i][6] + bv1.z; o1.w = acc[i][7] + bv1.w;
        out4[row * 256 + (n0 >> 2) + tx * 2]     = o0;
        out4[row * 256 + (n0 >> 2) + tx * 2 + 1] = o1;
    }
}

// ---------------------------------------------------------------------------
// Kernel B: recurrence, NON-CLUSTER (profileable!), register-resident weights.
// 128 blocks = 2 dir x 8 ugroups x 8 bgroups. Block owns 32 units x 8 batches.
// Per step: coalesced-load 8KB h slice (its 8 batches) from g_h into smem,
// register GEMV (R10 core), shfl-reduce, activations, store h, atomic barrier.
// ---------------------------------------------------------------------------
#define SHP 264   // smem h row pitch (floats)

__device__ __forceinline__ float fsigm(float x) {
    return __fdividef(1.f, 1.f + __expf(-x));
}
__device__ __forceinline__ float ftanh(float x) {
    float e = __expf(-2.f * fabsf(x));
    float r = __fdividef(1.f - e, 1.f + e);
    return copysignf(r, x);
}

__global__ void __launch_bounds__(256)
lstm_rec_kernel(const float* __restrict__ Whh_f,
                const float* __restrict__ Whh_b) {
    const int bid = blockIdx.x;
    const int dir = bid >> 6;
    const int ug  = (bid >> 3) & 7;     // unit group (32 units)
    const int bg  = bid & 7;            // batch group (8 batches)
    const int tid = threadIdx.x;        // 256
    const int u   = tid >> 3;           // 0..31 local unit
    const int kq  = tid & 7;            // k-slice / epilogue batch
    const int hu  = ug * 32 + u;
    const int bglob = bg * 8 + kq;

    const float* Whh = dir ? Whh_b : Whh_f;

    __shared__ __align__(16) float sH[8 * SHP];   // 8.25KB
    __shared__ __align__(16) float sDummy[8];     // keep alignment simple

    // weights in registers (loaded once)
    const float4* whh4 = (const float4*)Whh;
    float4 w[4][8];
#pragma unroll
    for (int g = 0; g < 4; ++g)
#pragma unroll
        for (int j = 0; j < 8; ++j)
            w[g][j] = whh4[((size_t)(g * 256 + hu)) * 64 + kq + j * 8];
    (void)sDummy;

    const float4* gh4 = (const float4*)g_h;

    // g_pre prefetch for first step
    const int t0 = dir ? 511 : 0;
    size_t pb = ((size_t)dir * 32768 + (size_t)t0 * 64 + bglob) * 1024 + hu;
    float4 pr;
    pr.x = __ldcg(&g_pre[pb]);
    pr.y = __ldcg(&g_pre[pb + 256]);
    pr.z = __ldcg(&g_pre[pb + 512]);
    pr.w = __ldcg(&g_pre[pb + 768]);

    float c = 0.f;

    for (int it = 0; it < 512; ++it) {
        const int t = dir ? (511 - it) : it;

        // ---- stage h(prev) for this block's 8 batches into smem ----
        if (it == 0) {
            float4 z = make_float4(0.f, 0.f, 0.f, 0.f);
#pragma unroll
            for (int s = 0; s < 2; ++s) {
                int e = tid + s * 256;            // 0..511
                int b_ = e >> 6, q = e & 63;
                *(float4*)&sH[b_ * SHP + q * 4] = z;
            }
        } else {
            const int tp = dir ? (t + 1) : (t - 1);
            size_t base = (((size_t)(dir * 512 + tp)) * 64 + bg * 8) * 64;
#pragma unroll
            for (int s = 0; s < 2; ++s) {
                int e = tid + s * 256;
                int b_ = e >> 6, q = e & 63;
                *(float4*)&sH[b_ * SHP + q * 4] = __ldcg(&gh4[base + b_ * 64 + q]);
            }
        }
        __syncthreads();

        // prefetch next step's g_pre
        float4 prn;
        if (it < 511) {
            const int tn = dir ? (t - 1) : (t + 1);
            size_t pbn = ((size_t)dir * 32768 + (size_t)tn * 64 + bglob) * 1024 + hu;
            prn.x = __ldcg(&g_pre[pbn]);
            prn.y = __ldcg(&g_pre[pbn + 256]);
            prn.z = __ldcg(&g_pre[pbn + 512]);
            prn.w = __ldcg(&g_pre[pbn + 768]);
        }

        // ---- register GEMV: acc[g][b] += w[g][:] . h[b][:] over k-slice ----
        float acc[4][8];
#pragma unroll
        for (int g = 0; g < 4; ++g)
#pragma unroll
            for (int b = 0; b < 8; ++b) acc[g][b] = 0.f;

        const float* hb = &sH[kq * 4];
#pragma unroll
        for (int j = 0; j < 8; ++j) {
#pragma unroll
            for (int b = 0; b < 8; ++b) {
                float4 h4 = *(const float4*)&hb[b * SHP + j * 32];
#pragma unroll
                for (int g = 0; g < 4; ++g) {
                    acc[g][b] = fmaf(w[g][j].x, h4.x,
                                fmaf(w[g][j].y, h4.y,
                                fmaf(w[g][j].z, h4.z,
                                fmaf(w[g][j].w, h4.w, acc[g][b]))));
                }
            }
        }

        // ---- reduce over 8 kq slices ----
#pragma unroll
        for (int g = 0; g < 4; ++g)
#pragma unroll
            for (int b = 0; b < 8; ++b) {
                float v = acc[g][b];
                v += __shfl_xor_sync(0xFFFFFFFFu, v, 1);
                v += __shfl_xor_sync(0xFFFFFFFFu, v, 2);
                v += __shfl_xor_sync(0xFFFFFFFFu, v, 4);
                acc[g][b] = v;
            }

        float s[4];
#pragma unroll
        for (int g = 0; g < 4; ++g) {
            float v = acc[g][0];
#pragma unroll
            for (int b = 1; b < 8; ++b) v = (kq == b) ? acc[g][b] : v;
            s[g] = v;
        }

        float gi = s[0] + pr.x;
        float gf = s[1] + pr.y;
        float gg = s[2] + pr.z;
        float go = s[3] + pr.w;

        float iv = fsigm(gi), fv = fsigm(gf), gv = ftanh(gg), ov = fsigm(go);
        c = fv * c + iv * gv;
        float hval = ov * ftanh(c);

        g_h[(((size_t)(dir * 512 + t)) * 64 + bglob) * 256 + hu] = hval;

        __syncthreads();   // sH reads done before next-step overwrite

        if (it < 511) {
            if (tid == 0) {
                __threadfence();
                atomicAdd(&g_bar, 1u);
                unsigned target = 128u * (unsigned)(it + 1);
                volatile unsigned* vb = &g_bar;
                while (*vb < target) { }
            }
            __syncthreads();
            __threadfence();
        }
        pr = prn;
    }
}

// ---------------------------------------------------------------------------
// Kernel C: logits (unchanged)
// ---------------------------------------------------------------------------
__global__ void logits_kernel(const float* __restrict__ Wout,
                              const float* __restrict__ bout) {
    const int t = blockIdx.x;
    __shared__ float sWo[10 * 512];
    __shared__ float sCH[64 * 65];
    __shared__ float sBo[10];

    const int tid = threadIdx.x;      // 640
    for (int idx = tid; idx < 5120; idx += 640) sWo[idx] = Wout[idx];
    if (tid < 10) sBo[tid] = bout[tid];

    const int n = tid / 64, bb = tid & 63;
    float acc = 0.f;
    const float4* gh4 = (const float4*)g_h;

    for (int ch = 0; ch < 8; ++ch) {
        __syncthreads();
        for (int idx = tid; idx < 1024; idx += 640) {
            int b_ = idx >> 4, q = idx & 15;
            int d = ch >> 2;
            int hid4 = (ch & 3) * 16 + q;
            float4 v = gh4[(((size_t)d * 512 + t) * 64 + b_) * 64 + hid4];
            float* dst = &sCH[(q * 4) * 65 + b_];
            dst[0]   = v.x;  dst[65]  = v.y;
            dst[130] = v.z;  dst[195] = v.w;
        }
        __syncthreads();
#pragma unroll 8
        for (int r = 0; r < 64; ++r)
            acc += sWo[n * 512 + ch * 64 + r] * sCH[r * 65 + bb];
    }
    g_logits[((size_t)t * 64 + bb) * 10 + n] = acc + sBo[n];
}

// ---------------------------------------------------------------------------
// Kernel D: Viterbi (unchanged, 63us)
// ---------------------------------------------------------------------------
__global__ void viterbi_kernel(const float* __restrict__ trans,
                               float* __restrict__ out) {
    const int tid  = threadIdx.x;
    const int w    = tid >> 5;
    const int lane = tid & 31;
    const int b    = blockIdx.x * 4 + w;

    __shared__ float         sLT[2][16][4][10];
    __shared__ float         sCur[4][32];
    __shared__ unsigned char bp[4][512][10];
    __shared__ float         tr[100];

    for (int i = tid; i < 100; i += 128) tr[i] = trans[i];

    const int bbase = blockIdx.x * 4;
    float stage[5];
#pragma unroll
    for (int s = 0; s < 5; ++s) {
        int idx = tid + s * 128;
        int t_off = idx / 40, rem = idx % 40;
        int b_off = rem / 10, k = rem % 10;
        stage[s] = g_logits[((size_t)(0 + t_off) * 64 + bbase + b_off) * 10 + k];
    }
#pragma unroll
    for (int s = 0; s < 5; ++s) {
        int idx = tid + s * 128;
        int t_off = idx / 40, rem = idx % 40;
        int b_off = rem / 10, k = rem % 10;
        sLT[0][t_off][b_off][k] = stage[s];
    }
    __syncthreads();

    float trc[10];
#pragma unroll
    for (int i = 0; i < 10; ++i) trc[i] = (lane < 10) ? tr[i * 10 + lane] : 0.f;

    float cur = (lane < 10) ? sLT[0][0][w][lane] : -1e30f;

    for (int cchunk = 0; cchunk < 32; ++cchunk) {
        const int buf = cchunk & 1;
        if (cchunk < 31) {
            const int tb = (cchunk + 1) * 16;
#pragma unroll
            for (int s = 0; s < 5; ++s) {
                int idx = tid + s * 128;
                int t_off = idx / 40, rem = idx % 40;
                int b_off = rem / 10, k = rem % 10;
                stage[s] = g_logits[((size_t)(tb + t_off) * 64 + bbase + b_off) * 10 + k];
            }
        }

        const int tstart = (cchunk == 0) ? 1 : 0;
#pragma unroll 4
        for (int ti = tstart; ti < 16; ++ti) {
            const int t = cchunk * 16 + ti;
            if (lane < 10) sCur[w][lane] = cur;
            __syncwarp();
            float best = sCur[w][0] + trc[0];
            int bi = 0;
#pragma unroll
            for (int i = 1; i < 10; ++i) {
                float v = sCur[w][i] + trc[i];
                if (v > best) { best = v; bi = i; }
            }
            __syncwarp();
            if (lane < 10) {
                cur = sLT[buf][ti][w][lane] + best;
                bp[w][t][lane] = (unsigned char)bi;
            }
        }

        if (cchunk < 31) {
            __syncthreads();
#pragma unroll
            for (int s = 0; s < 5; ++s) {
                int idx = tid + s * 128;
                int t_off = idx / 40, rem = idx % 40;
                int b_off = rem / 10, k = rem % 10;
                sLT[buf ^ 1][t_off][b_off][k] = stage[s];
            }
            __syncthreads();
        }
    }

    if (lane < 10) sCur[w][lane] = cur;
    __syncwarp();
    if (lane == 0) {
        float best = sCur[w][0]; int last = 0;
#pragma unroll
        for (int i = 1; i < 10; ++i)
            if (sCur[w][i] > best) { best = sCur[w][i]; last = i; }
        out[b] = best;
        float* po = out + 64 + (size_t)b * 512;
        int tag = last;
        po[511] = (float)tag;
        for (int t = 511; t >= 1; --t) {
            tag = bp[w][t][tag];
            po[t - 1] = (float)tag;
        }
    }
}

// ---------------------------------------------------------------------------
extern "C" void kernel_launch(void* const* d_in, const int* in_sizes, int n_in,
                              void* d_out, int out_size) {
    const int*   sent  = (const int*)  d_in[0];
    const float* emb   = (const float*)d_in[2];
    const float* Wih_f = (const float*)d_in[3];
    const float* Whh_f = (const float*)d_in[4];
    const float* b_f   = (const float*)d_in[5];
    const float* Wih_b = (const float*)d_in[6];
    const float* Whh_b = (const float*)d_in[7];
    const float* b_b   = (const float*)d_in[8];
    const float* W_out = (const float*)d_in[9];
    const float* b_out = (const float*)d_in[10];
    const float* trans = (const float*)d_in[11];
    float* out = (float*)d_out;

    // launches: 1 init, 2 pregemm, 3 dummy, 4 lstm_rec (ncu slot), 5 logits, 6 viterbi
    init_kernel<<<1, 1>>>();
    pregemm_kernel<<<dim3(8, 256, 2), 256>>>(sent, emb, Wih_f, b_f, Wih_b, b_b);
    dummy_kernel<<<1, 32>>>();
    lstm_rec_kernel<<<128, 256>>>(Whh_f, Whh_b);
    logits_kernel<<<512, 640>>>(W_out, b_out);
    viterbi_kernel<<<16, 128>>>(trans, out);
}